// round 1
// baseline (speedup 1.0000x reference)
#include <cuda_runtime.h>

// MultiGaussianDiffFusion: out = (w1+w2)*s + (w3-w2)*G3(s) + (w4-w3)*G5(s) - w4*G7(s)
// Separable depthwise Gaussians, fused into one tiled kernel.
// Shapes: s [4,48,512,512] f32; w1..w4 scalars (device). Output f32 same shape.

#define IMG_H 512
#define IMG_W 512
#define TX 64
#define TY 32
#define HALO 3
#define SW (TX + 2 * HALO)   // 70
#define SH (TY + 2 * HALO)   // 38
#define RPT 8                // rows per thread
#define NTHREADS 256

// Gaussian 1D coefficients (sigma per OpenCV rule: 0.8, 1.1, 1.4), normalized.
// Compile-time literals so ptxas emits FFMA-imm (rt=1).
#define K3_0 0.5220116f
#define K3_1 0.2389942f
#define K5_0 0.3695467f
#define K5_1 0.2444604f
#define K5_2 0.0707663f
#define K7_0 0.2880262f
#define K7_1 0.2231734f
#define K7_2 0.1038183f
#define K7_3 0.0289952f

__global__ void __launch_bounds__(NTHREADS, 2)
mgdf_kernel(const float* __restrict__ s,
            const float* __restrict__ w1p, const float* __restrict__ w2p,
            const float* __restrict__ w3p, const float* __restrict__ w4p,
            float* __restrict__ out)
{
    __shared__ float tile[SH][SW];

    const int img   = blockIdx.z;                       // 0..191 (b*C+c)
    const size_t base = (size_t)img * (IMG_H * IMG_W);
    const float* sp = s + base;
    float* op = out + base;

    const int tileX = blockIdx.x * TX;
    const int tileY = blockIdx.y * TY;
    const int tid = threadIdx.x;

    // ---- Stage 1: cooperative zero-padded tile load ----
    #pragma unroll
    for (int idx = tid; idx < SH * SW; idx += NTHREADS) {
        int r = idx / SW;
        int c = idx - r * SW;
        int gy = tileY - HALO + r;
        int gx = tileX - HALO + c;
        float v = 0.0f;
        if ((unsigned)gy < (unsigned)IMG_H && (unsigned)gx < (unsigned)IMG_W)
            v = __ldg(sp + gy * IMG_W + gx);
        tile[r][c] = v;
    }
    __syncthreads();

    const int tx = tid & (TX - 1);          // column within tile
    const int tz = tid >> 6;                // 0..3 row group
    const int colS = tx + HALO;             // smem center column
    const int rowBase = tz * RPT;           // smem row offset of first needed row

    // ---- Stage 2: horizontal pass (h3/h5/h7 for 14 rows, registers) ----
    float h3[RPT + 6], h5[RPT + 6], h7[RPT + 6], sc[RPT];
    #pragma unroll
    for (int r = 0; r < RPT + 6; r++) {
        const int sr = rowBase + r;
        float xm3 = tile[sr][colS - 3];
        float xm2 = tile[sr][colS - 2];
        float xm1 = tile[sr][colS - 1];
        float x0  = tile[sr][colS];
        float xp1 = tile[sr][colS + 1];
        float xp2 = tile[sr][colS + 2];
        float xp3 = tile[sr][colS + 3];
        float p1 = xm1 + xp1;
        float p2 = xm2 + xp2;
        float p3 = xm3 + xp3;
        h3[r] = K3_0 * x0 + K3_1 * p1;
        h5[r] = K5_0 * x0 + K5_1 * p1 + K5_2 * p2;
        h7[r] = K7_0 * x0 + K7_1 * p1 + K7_2 * p2 + K7_3 * p3;
        if (r >= HALO && r < HALO + RPT) sc[r - HALO] = x0;
    }

    // Runtime weight combine coefficients
    const float W1 = __ldg(w1p), W2 = __ldg(w2p), W3 = __ldg(w3p), W4 = __ldg(w4p);
    const float cA = W1 + W2;    // coef of s
    const float cB = W3 - W2;    // coef of s3
    const float cC = W4 - W3;    // coef of s5
    const float cD = -W4;        // coef of s7

    // ---- Stage 3: vertical pass + weighted combine + store ----
    #pragma unroll
    for (int k = 0; k < RPT; k++) {
        const int m = k + HALO;
        float v3 = K3_0 * h3[m] + K3_1 * (h3[m - 1] + h3[m + 1]);
        float v5 = K5_0 * h5[m] + K5_1 * (h5[m - 1] + h5[m + 1])
                                + K5_2 * (h5[m - 2] + h5[m + 2]);
        float v7 = K7_0 * h7[m] + K7_1 * (h7[m - 1] + h7[m + 1])
                                + K7_2 * (h7[m - 2] + h7[m + 2])
                                + K7_3 * (h7[m - 3] + h7[m + 3]);
        float o = cA * sc[k] + cB * v3 + cC * v5 + cD * v7;
        op[(tileY + rowBase + k) * IMG_W + (tileX + tx)] = o;
    }
}

extern "C" void kernel_launch(void* const* d_in, const int* in_sizes, int n_in,
                              void* d_out, int out_size)
{
    const float* s  = (const float*)d_in[0];
    const float* w1 = (const float*)d_in[1];
    const float* w2 = (const float*)d_in[2];
    const float* w3 = (const float*)d_in[3];
    const float* w4 = (const float*)d_in[4];
    float* out = (float*)d_out;

    const int n_img = in_sizes[0] / (IMG_H * IMG_W);   // 192
    dim3 grid(IMG_W / TX, IMG_H / TY, n_img);          // (8, 16, 192)
    mgdf_kernel<<<grid, NTHREADS>>>(s, w1, w2, w3, w4, out);
}

// round 2
// speedup vs baseline: 1.6994x; 1.6994x over previous
#include <cuda_runtime.h>

typedef unsigned long long ull;

// out = (w1+w2)*s + (w3-w2)*G3(s) + (w4-w3)*G5(s) - w4*G7(s)
// Separable Gaussians: scalar horizontal pass (FFMA-imm), packed f32x2 vertical pass.

#define IMG 512
#define TX 128
#define TY 64
#define NTH 256
#define SW 136            // TX + 8 (left halo 4 for alignment, right halo 4)
#define SH 70             // TY + 6
#define NF4 (SW / 4)      // 34 float4 per smem row

// Gaussian 1D coefficients (sigma 0.8 / 1.1 / 1.4 per OpenCV rule), normalized.
#define K3_0 0.5220116f
#define K3_1 0.2389942f
#define K5_0 0.3695467f
#define K5_1 0.2444604f
#define K5_2 0.0707663f
#define K7_0 0.2880262f
#define K7_1 0.2231734f
#define K7_2 0.1038183f
#define K7_3 0.0289952f

__device__ __forceinline__ ull pk2(float lo, float hi) {
    ull r; asm("mov.b64 %0, {%1, %2};" : "=l"(r) : "f"(lo), "f"(hi)); return r;
}
__device__ __forceinline__ ull add2(ull a, ull b) {
    ull r; asm("add.rn.f32x2 %0, %1, %2;" : "=l"(r) : "l"(a), "l"(b)); return r;
}
__device__ __forceinline__ ull mul2(ull a, ull b) {
    ull r; asm("mul.rn.f32x2 %0, %1, %2;" : "=l"(r) : "l"(a), "l"(b)); return r;
}
__device__ __forceinline__ ull fma2(ull a, ull b, ull c) {
    ull r; asm("fma.rn.f32x2 %0, %1, %2, %3;" : "=l"(r) : "l"(a), "l"(b), "l"(c)); return r;
}

__global__ void __launch_bounds__(NTH, 2)
mgdf_kernel(const float* __restrict__ s,
            const float* __restrict__ w1p, const float* __restrict__ w2p,
            const float* __restrict__ w3p, const float* __restrict__ w4p,
            float* __restrict__ out)
{
    __shared__ __align__(16) float tile[SH][SW];

    const int img = blockIdx.z;
    const size_t base = (size_t)img * (IMG * IMG);
    const float* sp = s + base;
    float* op = out + base;

    const int tileX = blockIdx.x * TX;
    const int tileY = blockIdx.y * TY;
    const int tid = threadIdx.x;

    // ---- Stage 1: aligned float4 tile load (smem col = gx - tileX + 4) ----
    // gx is always a multiple of 4; partial-OOB float4s are in fact fully OOB,
    // so a single unsigned bound check per float4 is exact.
    #pragma unroll
    for (int idx = tid; idx < SH * NF4; idx += NTH) {
        int r = idx / NF4;
        int c4 = idx - r * NF4;
        int gy = tileY - 3 + r;
        int gx = tileX - 4 + c4 * 4;
        float4 v = make_float4(0.f, 0.f, 0.f, 0.f);
        if ((unsigned)gy < (unsigned)IMG && (unsigned)gx < (unsigned)IMG)
            v = *reinterpret_cast<const float4*>(sp + gy * IMG + gx);
        *reinterpret_cast<float4*>(&tile[r][c4 * 4]) = v;
    }
    __syncthreads();

    // ---- Weights: fold combine into vertical coefficients ----
    const float W1 = __ldg(w1p), W2 = __ldg(w2p), W3 = __ldg(w3p), W4 = __ldg(w4p);
    const float cA = W1 + W2;          // coef of raw s
    const float cB = W3 - W2;          // coef of G3
    const float cC = W4 - W3;          // coef of G5
    const float cD = -W4;              // coef of G7
    const ull cAp = pk2(cA, cA);
    const ull a30 = pk2(cB * K3_0, cB * K3_0);
    const ull a31 = pk2(cB * K3_1, cB * K3_1);
    const ull a50 = pk2(cC * K5_0, cC * K5_0);
    const ull a51 = pk2(cC * K5_1, cC * K5_1);
    const ull a52 = pk2(cC * K5_2, cC * K5_2);
    const ull a70 = pk2(cD * K7_0, cD * K7_0);
    const ull a71 = pk2(cD * K7_1, cD * K7_1);
    const ull a72 = pk2(cD * K7_2, cD * K7_2);
    const ull a73 = pk2(cD * K7_3, cD * K7_3);

    const int xg = tid & 31;          // 32 column-groups of 4 cols -> 128 cols
    const int rg = tid >> 5;          // 8 row-groups
    const int cb = 4 * xg;            // smem col of x[0]; taps j=1..10, center j=4+i
    const int rowBase = rg * 8;       // first smem row needed

    // Rolling register windows (full unroll -> constant indices -> registers)
    ull h3p[14][2], h5p[14][2], h7p[14][2];

    #pragma unroll
    for (int k = 0; k < 14; k++) {
        const int sr = rowBase + k;

        // ---- Stage 2: horizontal pass, 4 columns, scalar FFMA-imm ----
        float4 A = *reinterpret_cast<const float4*>(&tile[sr][cb]);
        float4 B = *reinterpret_cast<const float4*>(&tile[sr][cb + 4]);
        float4 C = *reinterpret_cast<const float4*>(&tile[sr][cb + 8]);
        float x[12] = {A.x, A.y, A.z, A.w, B.x, B.y, B.z, B.w, C.x, C.y, C.z, C.w};
        float h3[4], h5[4], h7[4];
        #pragma unroll
        for (int i = 0; i < 4; i++) {
            float p1 = x[i + 3] + x[i + 5];
            float p2 = x[i + 2] + x[i + 6];
            float p3 = x[i + 1] + x[i + 7];
            float x0 = x[i + 4];
            h3[i] = K3_0 * x0 + K3_1 * p1;
            h5[i] = K5_0 * x0 + K5_1 * p1 + K5_2 * p2;
            h7[i] = K7_0 * x0 + K7_1 * p1 + K7_2 * p2 + K7_3 * p3;
        }
        h3p[k][0] = pk2(h3[0], h3[1]);  h3p[k][1] = pk2(h3[2], h3[3]);
        h5p[k][0] = pk2(h5[0], h5[1]);  h5p[k][1] = pk2(h5[2], h5[3]);
        h7p[k][0] = pk2(h7[0], h7[1]);  h7p[k][1] = pk2(h7[2], h7[3]);

        // ---- Stage 3: vertical pass (packed f32x2) once window is full ----
        if (k >= 6) {
            const int m = k - 3;                 // center row index in h arrays
            const int cr = rowBase + m;          // smem row of output center
            // raw-center pairs, 8B-aligned LDS.64
            ull s0 = *reinterpret_cast<const ull*>(&tile[cr][cb + 4]);
            ull s1 = *reinterpret_cast<const ull*>(&tile[cr][cb + 6]);

            ull acc0 = mul2(cAp, s0);
            ull acc1 = mul2(cAp, s1);
            acc0 = fma2(a30, h3p[m][0], acc0);
            acc1 = fma2(a30, h3p[m][1], acc1);
            acc0 = fma2(a31, add2(h3p[m - 1][0], h3p[m + 1][0]), acc0);
            acc1 = fma2(a31, add2(h3p[m - 1][1], h3p[m + 1][1]), acc1);
            acc0 = fma2(a50, h5p[m][0], acc0);
            acc1 = fma2(a50, h5p[m][1], acc1);
            acc0 = fma2(a51, add2(h5p[m - 1][0], h5p[m + 1][0]), acc0);
            acc1 = fma2(a51, add2(h5p[m - 1][1], h5p[m + 1][1]), acc1);
            acc0 = fma2(a52, add2(h5p[m - 2][0], h5p[m + 2][0]), acc0);
            acc1 = fma2(a52, add2(h5p[m - 2][1], h5p[m + 2][1]), acc1);
            acc0 = fma2(a70, h7p[m][0], acc0);
            acc1 = fma2(a70, h7p[m][1], acc1);
            acc0 = fma2(a71, add2(h7p[m - 1][0], h7p[m + 1][0]), acc0);
            acc1 = fma2(a71, add2(h7p[m - 1][1], h7p[m + 1][1]), acc1);
            acc0 = fma2(a72, add2(h7p[m - 2][0], h7p[m + 2][0]), acc0);
            acc1 = fma2(a72, add2(h7p[m - 2][1], h7p[m + 2][1]), acc1);
            acc0 = fma2(a73, add2(h7p[m - 3][0], h7p[m + 3][0]), acc0);
            acc1 = fma2(a73, add2(h7p[m - 3][1], h7p[m + 3][1]), acc1);

            ulonglong2 o;
            o.x = acc0;
            o.y = acc1;
            *reinterpret_cast<ulonglong2*>(
                op + (size_t)(tileY + rowBase + k - 6) * IMG + tileX + cb) = o;
        }
    }
}

extern "C" void kernel_launch(void* const* d_in, const int* in_sizes, int n_in,
                              void* d_out, int out_size)
{
    const float* s  = (const float*)d_in[0];
    const float* w1 = (const float*)d_in[1];
    const float* w2 = (const float*)d_in[2];
    const float* w3 = (const float*)d_in[3];
    const float* w4 = (const float*)d_in[4];
    float* out = (float*)d_out;

    const int n_img = in_sizes[0] / (IMG * IMG);       // 192
    dim3 grid(IMG / TX, IMG / TY, n_img);              // (4, 8, 192)
    mgdf_kernel<<<grid, NTH>>>(s, w1, w2, w3, w4, out);
}

// round 3
// speedup vs baseline: 1.9857x; 1.1685x over previous
#include <cuda_runtime.h>

typedef unsigned long long ull;

// out = (w1+w2)*s + (w3-w2)*G3(s) + (w4-w3)*G5(s) - w4*G7(s)
// Separable Gaussians. Scalar horizontal (FFMA-imm), packed f32x2 vertical with
// rolling register windows. 2 cols/thread, 16 rows/thread, 3 CTAs/SM.

#define IMG 512
#define TX 128
#define TY 64
#define NTH 256
#define SW 136            // TX + 8 (left halo 4 for f4 alignment, right halo 4)
#define SH 70             // TY + 6
#define NF4 (SW / 4)      // 34
#define STEPS 22          // 16 output rows + 6 halo rows

#define K3_0 0.5220116f
#define K3_1 0.2389942f
#define K5_0 0.3695467f
#define K5_1 0.2444604f
#define K5_2 0.0707663f
#define K7_0 0.2880262f
#define K7_1 0.2231734f
#define K7_2 0.1038183f
#define K7_3 0.0289952f

__device__ __forceinline__ ull pk2(float lo, float hi) {
    ull r; asm("mov.b64 %0, {%1, %2};" : "=l"(r) : "f"(lo), "f"(hi)); return r;
}
__device__ __forceinline__ ull add2(ull a, ull b) {
    ull r; asm("add.rn.f32x2 %0, %1, %2;" : "=l"(r) : "l"(a), "l"(b)); return r;
}
__device__ __forceinline__ ull mul2(ull a, ull b) {
    ull r; asm("mul.rn.f32x2 %0, %1, %2;" : "=l"(r) : "l"(a), "l"(b)); return r;
}
__device__ __forceinline__ ull fma2(ull a, ull b, ull c) {
    ull r; asm("fma.rn.f32x2 %0, %1, %2, %3;" : "=l"(r) : "l"(a), "l"(b), "l"(c)); return r;
}

__global__ void __launch_bounds__(NTH, 3)
mgdf_kernel(const float* __restrict__ s,
            const float* __restrict__ w1p, const float* __restrict__ w2p,
            const float* __restrict__ w3p, const float* __restrict__ w4p,
            float* __restrict__ out)
{
    __shared__ __align__(16) float tile[SH][SW];

    const int img = blockIdx.z;
    const size_t base = (size_t)img * (IMG * IMG);
    const float* sp = s + base;
    float* op = out + base;

    const int tileX = blockIdx.x * TX;
    const int tileY = blockIdx.y * TY;
    const int tid = threadIdx.x;

    // ---- Stage 1: aligned float4 tile load, zero-padded ----
    #pragma unroll
    for (int idx = tid; idx < SH * NF4; idx += NTH) {
        int r = idx / NF4;
        int c4 = idx - r * NF4;
        int gy = tileY - 3 + r;
        int gx = tileX - 4 + c4 * 4;
        float4 v = make_float4(0.f, 0.f, 0.f, 0.f);
        if ((unsigned)gy < (unsigned)IMG && (unsigned)gx < (unsigned)IMG)
            v = *reinterpret_cast<const float4*>(sp + gy * IMG + gx);
        *reinterpret_cast<float4*>(&tile[r][c4 * 4]) = v;
    }
    __syncthreads();

    // ---- Runtime weights folded into vertical coefficients ----
    const float W1 = __ldg(w1p), W2 = __ldg(w2p), W3 = __ldg(w3p), W4 = __ldg(w4p);
    const float cA = W1 + W2;
    const float cB = W3 - W2;
    const float cC = W4 - W3;
    const float cD = -W4;
    const ull cAp = pk2(cA, cA);
    const ull a30 = pk2(cB * K3_0, cB * K3_0);
    const ull a31 = pk2(cB * K3_1, cB * K3_1);
    const ull a50 = pk2(cC * K5_0, cC * K5_0);
    const ull a51 = pk2(cC * K5_1, cC * K5_1);
    const ull a52 = pk2(cC * K5_2, cC * K5_2);
    const ull a70 = pk2(cD * K7_0, cD * K7_0);
    const ull a71 = pk2(cD * K7_1, cD * K7_1);
    const ull a72 = pk2(cD * K7_2, cD * K7_2);
    const ull a73 = pk2(cD * K7_3, cD * K7_3);

    const int xg = tid & 63;            // 64 column groups of 2 cols
    const int rg = tid >> 6;            // 4 row groups of 16 rows
    const int cs = 2 * xg + 4;          // smem col of this thread's first center
    const int rowBase = rg * 16;        // smem row of first streamed row

    // Rolling windows (modulo indices are compile-time under full unroll)
    ull w7[6], w5[5], w3[4];

    #pragma unroll
    for (int k = 0; k < STEPS; k++) {
        const int sr = rowBase + k;

        // ---- horizontal pass for smem row sr, cols cs,cs+1 (scalar, imm FMA) ----
        float  x1 = tile[sr][cs - 3];
        float2 P1 = *reinterpret_cast<const float2*>(&tile[sr][cs - 2]);
        float2 P2 = *reinterpret_cast<const float2*>(&tile[sr][cs]);
        float2 P3 = *reinterpret_cast<const float2*>(&tile[sr][cs + 2]);
        float  x8 = tile[sr][cs + 4];

        // col0 taps: x1,P1.x,P1.y,P2.x(c),P2.y,P3.x,P3.y
        float a_p1 = P1.y + P2.y;
        float a_p2 = P1.x + P3.x;
        float a_p3 = x1 + P3.y;
        float h3a = K3_0 * P2.x + K3_1 * a_p1;
        float h5a = K5_0 * P2.x + K5_1 * a_p1 + K5_2 * a_p2;
        float h7a = K7_0 * P2.x + K7_1 * a_p1 + K7_2 * a_p2 + K7_3 * a_p3;
        // col1 taps: P1.x..x8, center P2.y
        float b_p1 = P2.x + P3.x;
        float b_p2 = P1.y + P3.y;
        float b_p3 = P1.x + x8;
        float h3b = K3_0 * P2.y + K3_1 * b_p1;
        float h5b = K5_0 * P2.y + K5_1 * b_p1 + K5_2 * b_p2;
        float h7b = K7_0 * P2.y + K7_1 * b_p1 + K7_2 * b_p2 + K7_3 * b_p3;

        ull t3 = pk2(h3a, h3b);
        ull t5 = pk2(h5a, h5b);
        ull t7 = pk2(h7a, h7b);

        // ---- vertical pass (center smem row = sr-3) once windows are full ----
        if (k >= 6) {
            ull C = *reinterpret_cast<const ull*>(&tile[sr - 3][cs]);
            ull acc = mul2(cAp, C);
            acc = fma2(a30, w3[(k - 3) % 4], acc);
            acc = fma2(a31, add2(w3[(k - 4) % 4], w3[(k - 2) % 4]), acc);
            acc = fma2(a50, w5[(k - 3) % 5], acc);
            acc = fma2(a51, add2(w5[(k - 4) % 5], w5[(k - 2) % 5]), acc);
            acc = fma2(a52, add2(w5[(k - 5) % 5], w5[(k - 1) % 5]), acc);
            acc = fma2(a70, w7[(k - 3) % 6], acc);
            acc = fma2(a71, add2(w7[(k - 4) % 6], w7[(k - 2) % 6]), acc);
            acc = fma2(a72, add2(w7[(k - 5) % 6], w7[(k - 1) % 6]), acc);
            acc = fma2(a73, add2(w7[(k - 6) % 6], t7), acc);

            *reinterpret_cast<ull*>(
                op + (size_t)(tileY + rowBase + k - 6) * IMG + tileX + 2 * xg) = acc;
        }

        // push this row into the windows
        w7[k % 6] = t7;
        w5[k % 5] = t5;
        w3[k % 4] = t3;
    }
}

extern "C" void kernel_launch(void* const* d_in, const int* in_sizes, int n_in,
                              void* d_out, int out_size)
{
    const float* s  = (const float*)d_in[0];
    const float* w1 = (const float*)d_in[1];
    const float* w2 = (const float*)d_in[2];
    const float* w3 = (const float*)d_in[3];
    const float* w4 = (const float*)d_in[4];
    float* out = (float*)d_out;

    const int n_img = in_sizes[0] / (IMG * IMG);       // 192
    dim3 grid(IMG / TX, IMG / TY, n_img);              // (4, 8, 192)
    mgdf_kernel<<<grid, NTH>>>(s, w1, w2, w3, w4, out);
}

// round 4
// speedup vs baseline: 2.1001x; 1.0576x over previous
#include <cuda_runtime.h>

typedef unsigned long long ull;

// out = (w1+w2)*s + (w3-w2)*G3(s) + (w4-w3)*G5(s) - w4*G7(s)
// Separable Gaussians. Scalar horizontal (FFMA-imm), transposed-FIR vertical in
// packed f32x2 with a 7-slot accumulator ring. 2 cols/thread, 16 rows/thread,
// 4 CTAs/SM.

#define IMG 512
#define TX 128
#define TY 64
#define NTH 256
#define SW 136            // TX + 8 (left halo 4 for f4 alignment, right halo 4)
#define SH 70             // TY + 6
#define NF4 (SW / 4)      // 34
#define STEPS 22          // 16 output rows + 6 halo rows

#define K3_0 0.5220116f
#define K3_1 0.2389942f
#define K5_0 0.3695467f
#define K5_1 0.2444604f
#define K5_2 0.0707663f
#define K7_0 0.2880262f
#define K7_1 0.2231734f
#define K7_2 0.1038183f
#define K7_3 0.0289952f

__device__ __forceinline__ ull pk2(float lo, float hi) {
    ull r; asm("mov.b64 %0, {%1, %2};" : "=l"(r) : "f"(lo), "f"(hi)); return r;
}
__device__ __forceinline__ ull mul2(ull a, ull b) {
    ull r; asm("mul.rn.f32x2 %0, %1, %2;" : "=l"(r) : "l"(a), "l"(b)); return r;
}
__device__ __forceinline__ ull fma2(ull a, ull b, ull c) {
    ull r; asm("fma.rn.f32x2 %0, %1, %2, %3;" : "=l"(r) : "l"(a), "l"(b), "l"(c)); return r;
}

__global__ void __launch_bounds__(NTH, 4)
mgdf_kernel(const float* __restrict__ s,
            const float* __restrict__ w1p, const float* __restrict__ w2p,
            const float* __restrict__ w3p, const float* __restrict__ w4p,
            float* __restrict__ out)
{
    __shared__ __align__(16) float tile[SH][SW];

    const int img = blockIdx.z;
    const size_t base = (size_t)img * (IMG * IMG);
    const float* sp = s + base;
    float* op = out + base;

    const int tileX = blockIdx.x * TX;
    const int tileY = blockIdx.y * TY;
    const int tid = threadIdx.x;

    // ---- Stage 1: aligned float4 tile load, zero-padded ----
    #pragma unroll
    for (int idx = tid; idx < SH * NF4; idx += NTH) {
        int r = idx / NF4;
        int c4 = idx - r * NF4;
        int gy = tileY - 3 + r;
        int gx = tileX - 4 + c4 * 4;
        float4 v = make_float4(0.f, 0.f, 0.f, 0.f);
        if ((unsigned)gy < (unsigned)IMG && (unsigned)gx < (unsigned)IMG)
            v = *reinterpret_cast<const float4*>(sp + gy * IMG + gx);
        *reinterpret_cast<float4*>(&tile[r][c4 * 4]) = v;
    }
    __syncthreads();

    // ---- Runtime weights folded into vertical coefficients ----
    const float W1 = *w1p, W2 = *w2p, W3 = *w3p, W4 = *w4p;
    const float cA = W1 + W2;
    const float cB = W3 - W2;
    const float cC = W4 - W3;
    const float cD = -W4;
    const ull cAp = pk2(cA, cA);
    const ull a30 = pk2(cB * K3_0, cB * K3_0);
    const ull a31 = pk2(cB * K3_1, cB * K3_1);
    const ull a50 = pk2(cC * K5_0, cC * K5_0);
    const ull a51 = pk2(cC * K5_1, cC * K5_1);
    const ull a52 = pk2(cC * K5_2, cC * K5_2);
    const ull a70 = pk2(cD * K7_0, cD * K7_0);
    const ull a71 = pk2(cD * K7_1, cD * K7_1);
    const ull a72 = pk2(cD * K7_2, cD * K7_2);
    const ull a73 = pk2(cD * K7_3, cD * K7_3);

    const int xg = tid & 63;            // 64 column groups of 2 cols
    const int rg = tid >> 6;            // 4 row groups of 16 rows
    const int cs = 2 * xg + 4;          // smem col of this thread's first center
    const int rowBase = rg * 16;        // smem row of first streamed row
    float* orow = op + (size_t)(tileY + rowBase) * IMG + tileX + 2 * xg;

    // 7-slot accumulator ring (transposed FIR); indices compile-time under unroll
    ull acc[7];

    #pragma unroll
    for (int k = 0; k < STEPS; k++) {
        const int sr = rowBase + k;

        // ---- horizontal pass, cols cs,cs+1 (scalar, literal-imm FFMA) ----
        float  x1 = tile[sr][cs - 3];
        float2 P1 = *reinterpret_cast<const float2*>(&tile[sr][cs - 2]);
        float2 P2 = *reinterpret_cast<const float2*>(&tile[sr][cs]);
        float2 P3 = *reinterpret_cast<const float2*>(&tile[sr][cs + 2]);
        float  x8 = tile[sr][cs + 4];

        float a_p1 = P1.y + P2.y;
        float a_p2 = P1.x + P3.x;
        float a_p3 = x1 + P3.y;
        float h3a = K3_0 * P2.x + K3_1 * a_p1;
        float h5a = K5_0 * P2.x + K5_1 * a_p1 + K5_2 * a_p2;
        float h7a = K7_0 * P2.x + K7_1 * a_p1 + K7_2 * a_p2 + K7_3 * a_p3;

        float b_p1 = P2.x + P3.x;
        float b_p2 = P1.y + P3.y;
        float b_p3 = P1.x + x8;
        float h3b = K3_0 * P2.y + K3_1 * b_p1;
        float h5b = K5_0 * P2.y + K5_1 * b_p1 + K5_2 * b_p2;
        float h7b = K7_0 * P2.y + K7_1 * b_p1 + K7_2 * b_p2 + K7_3 * b_p3;

        ull t3 = pk2(h3a, h3b);
        ull t5 = pk2(h5a, h5b);
        ull t7 = pk2(h7a, h7b);
        ull rw = pk2(P2.x, P2.y);

        // ---- transposed vertical: scatter row k into in-flight outputs ----
        // output m = k - d, valid if 0 <= m <= 15
        if (k <= 15) {                                   // d=0 (init slot)
            acc[k % 7] = mul2(a73, t7);
        }
        if (k >= 1 && k <= 16) {                         // d=1
            ull a = acc[(k - 1) % 7];
            a = fma2(a72, t7, a);
            a = fma2(a52, t5, a);
            acc[(k - 1) % 7] = a;
        }
        if (k >= 2 && k <= 17) {                         // d=2
            ull a = acc[(k - 2) % 7];
            a = fma2(a71, t7, a);
            a = fma2(a51, t5, a);
            a = fma2(a31, t3, a);
            acc[(k - 2) % 7] = a;
        }
        if (k >= 3 && k <= 18) {                         // d=3 (center)
            ull a = acc[(k - 3) % 7];
            a = fma2(a70, t7, a);
            a = fma2(a50, t5, a);
            a = fma2(a30, t3, a);
            a = fma2(cAp, rw, a);
            acc[(k - 3) % 7] = a;
        }
        if (k >= 4 && k <= 19) {                         // d=4
            ull a = acc[(k - 4) % 7];
            a = fma2(a71, t7, a);
            a = fma2(a51, t5, a);
            a = fma2(a31, t3, a);
            acc[(k - 4) % 7] = a;
        }
        if (k >= 5 && k <= 20) {                         // d=5
            ull a = acc[(k - 5) % 7];
            a = fma2(a72, t7, a);
            a = fma2(a52, t5, a);
            acc[(k - 5) % 7] = a;
        }
        if (k >= 6) {                                    // d=6: finish + store
            ull r = fma2(a73, t7, acc[(k - 6) % 7]);
            *reinterpret_cast<ull*>(orow + (size_t)(k - 6) * IMG) = r;
        }
    }
}

extern "C" void kernel_launch(void* const* d_in, const int* in_sizes, int n_in,
                              void* d_out, int out_size)
{
    const float* s  = (const float*)d_in[0];
    const float* w1 = (const float*)d_in[1];
    const float* w2 = (const float*)d_in[2];
    const float* w3 = (const float*)d_in[3];
    const float* w4 = (const float*)d_in[4];
    float* out = (float*)d_out;

    const int n_img = in_sizes[0] / (IMG * IMG);       // 192
    dim3 grid(IMG / TX, IMG / TY, n_img);              // (4, 8, 192)
    mgdf_kernel<<<grid, NTH>>>(s, w1, w2, w3, w4, out);
}